// round 1
// baseline (speedup 1.0000x reference)
#include <cuda_runtime.h>
#include <cuda_bf16.h>
#include <math.h>

// Problem constants
#define B_  2
#define S_  2048
#define D_  2048
#define H_  16
#define DH  128
#define MROWS (B_ * S_)          // 4096

// ---------------------------------------------------------------------------
// Scratch (static __device__ arrays; no allocation anywhere)
// ---------------------------------------------------------------------------
__device__ float g_tq[(size_t)B_ * S_ * D_];                 // tmp q  [B,S,D]
__device__ float g_tk[(size_t)B_ * S_ * D_];                 // tmp k
__device__ float g_tv[(size_t)B_ * S_ * D_];                 // tmp v
__device__ float g_q [(size_t)B_ * H_ * S_ * DH];            // roped q [B,H,S,Dh]
__device__ float g_k [(size_t)B_ * H_ * S_ * DH];            // roped k
__device__ float g_v [(size_t)B_ * H_ * S_ * DH];            // permuted v
__device__ float g_sc[(size_t)B_ * H_ * S_ * S_];            // scores/probs (537MB)
__device__ float g_ctx[(size_t)B_ * S_ * D_];                // attention output [B,S,D]

// ---------------------------------------------------------------------------
// SGEMM: C = scale * (A @ op(B)) + bias
//   A: [M,K] row-major (row stride == K in all call sites)
//   TRANSB=1: B is [N,K] row-major (C = A @ B^T)
//   TRANSB=0: B is [K,N] row-major (C = A @ B)
// Batched via blockIdx.z with simple strides; C batch offset supports the
// head-split layout: off = (z / cDiv) * cS1 + (z % cDiv) * cS2.
// Tiles: 128x128x8, 256 threads, 8x8 per-thread microtile, double-buffered.
// All dims used here are multiples of the tile sizes -> no predication.
// ---------------------------------------------------------------------------
#define BM 128
#define BN 128
#define BK 8

template <int TRANSB>
__global__ __launch_bounds__(256)
void sgemm_kernel(const float* __restrict__ A,
                  const float* __restrict__ Bm,
                  float* __restrict__ C,
                  int M, int N, int K,
                  long aBatch, long bBatch,
                  int cDiv, long cS1, long cS2, int ldc,
                  const float* __restrict__ bias,
                  float scale)
{
    const int z = blockIdx.z;
    A  += (long)z * aBatch;
    Bm += (long)z * bBatch;
    C  += (long)(z / cDiv) * cS1 + (long)(z % cDiv) * cS2;

    __shared__ float As[2][BK][BM];
    __shared__ float Bs[2][BK][BN];

    const int tid = threadIdx.x;
    const int bm = blockIdx.y * BM;
    const int bn = blockIdx.x * BN;

    // global-load assignments
    const int arow = tid >> 1;            // 0..127
    const int acol = (tid & 1) * 4;       // 0 or 4
    int brow, bcol;
    if (TRANSB) { brow = tid >> 1; bcol = (tid & 1) * 4; }
    else        { brow = tid >> 5; bcol = (tid & 31) * 4; }

    const float* Ap = A + (long)(bm + arow) * K + acol;
    const float* Bp = TRANSB ? (Bm + (long)(bn + brow) * K + bcol)
                             : (Bm + (long)brow * N + bn + bcol);

    const int ty = tid >> 4;   // 0..15
    const int tx = tid & 15;   // 0..15

    float acc[8][8];
#pragma unroll
    for (int i = 0; i < 8; i++)
#pragma unroll
        for (int j = 0; j < 8; j++) acc[i][j] = 0.f;

    // prologue: stage tile 0
    {
        float4 af = *(const float4*)Ap;
        As[0][acol + 0][arow] = af.x;
        As[0][acol + 1][arow] = af.y;
        As[0][acol + 2][arow] = af.z;
        As[0][acol + 3][arow] = af.w;
        float4 bf = *(const float4*)Bp;
        if (TRANSB) {
            Bs[0][bcol + 0][brow] = bf.x;
            Bs[0][bcol + 1][brow] = bf.y;
            Bs[0][bcol + 2][brow] = bf.z;
            Bs[0][bcol + 3][brow] = bf.w;
        } else {
            *(float4*)&Bs[0][brow][bcol] = bf;
        }
    }
    __syncthreads();

    const int nk = K / BK;
    for (int kt = 0; kt < nk; ++kt) {
        const int cur = kt & 1;
        const bool has_next = (kt + 1 < nk);
        float4 an, bq;
        if (has_next) {
            an = *(const float4*)(Ap + (kt + 1) * BK);
            bq = TRANSB ? *(const float4*)(Bp + (kt + 1) * BK)
                        : *(const float4*)(Bp + (long)(kt + 1) * BK * N);
        }

#pragma unroll
        for (int kk = 0; kk < BK; ++kk) {
            float a[8], b[8];
            *(float4*)(a)     = *(const float4*)&As[cur][kk][ty * 4];
            *(float4*)(a + 4) = *(const float4*)&As[cur][kk][64 + ty * 4];
            *(float4*)(b)     = *(const float4*)&Bs[cur][kk][tx * 4];
            *(float4*)(b + 4) = *(const float4*)&Bs[cur][kk][64 + tx * 4];
#pragma unroll
            for (int i = 0; i < 8; i++)
#pragma unroll
                for (int j = 0; j < 8; j++)
                    acc[i][j] = fmaf(a[i], b[j], acc[i][j]);
        }

        if (has_next) {
            const int nx = cur ^ 1;
            As[nx][acol + 0][arow] = an.x;
            As[nx][acol + 1][arow] = an.y;
            As[nx][acol + 2][arow] = an.z;
            As[nx][acol + 3][arow] = an.w;
            if (TRANSB) {
                Bs[nx][bcol + 0][brow] = bq.x;
                Bs[nx][bcol + 1][brow] = bq.y;
                Bs[nx][bcol + 2][brow] = bq.z;
                Bs[nx][bcol + 3][brow] = bq.w;
            } else {
                *(float4*)&Bs[nx][brow][bcol] = bq;
            }
            __syncthreads();
        }
    }

    // epilogue
#pragma unroll
    for (int i = 0; i < 8; i++) {
        const int gm = bm + ((i < 4) ? (ty * 4 + i) : (64 + ty * 4 + i - 4));
#pragma unroll
        for (int j = 0; j < 8; j++) {
            const int gn = bn + ((j < 4) ? (tx * 4 + j) : (64 + tx * 4 + j - 4));
            float v = acc[i][j] * scale;
            if (bias) v += bias[gn];
            C[(long)gm * ldc + gn] = v;
        }
    }
}

// ---------------------------------------------------------------------------
// RoPE + permute [B,S,H,Dh] -> [B,H,S,Dh]; v is permute-only.
// One thread per (b,h,s,j) with j in [0,64): handles the (j, j+64) pair.
// ---------------------------------------------------------------------------
__global__ __launch_bounds__(256)
void rope_permute_kernel()
{
    const int HALF = DH / 2;     // 64
    long idx = (long)blockIdx.x * blockDim.x + threadIdx.x;
    const long total = (long)B_ * H_ * S_ * HALF;
    if (idx >= total) return;

    const int j = (int)(idx % HALF);
    const int s = (int)((idx / HALF) % S_);
    const int h = (int)((idx / ((long)HALF * S_)) % H_);
    const int b = (int)(idx / ((long)HALF * S_ * H_));

    const long off_in  = ((long)(b * S_ + s)) * D_ + h * DH + j;
    const long off_out = (((long)(b * H_ + h) * S_) + s) * DH + j;

    // inv_freq = 10000^(-j/64); theta = s * inv_freq  (match jax fp32 math)
    const float inv = expf(-(float)j * (9.210340371976184f / 64.0f)); // ln(10000)
    const float th  = (float)s * inv;
    const float c = cosf(th);
    const float sn = sinf(th);

    {
        const float x1 = g_tq[off_in];
        const float x2 = g_tq[off_in + HALF];
        g_q[off_out]        = x1 * c - x2 * sn;
        g_q[off_out + HALF] = x2 * c + x1 * sn;
    }
    {
        const float x1 = g_tk[off_in];
        const float x2 = g_tk[off_in + HALF];
        g_k[off_out]        = x1 * c - x2 * sn;
        g_k[off_out + HALF] = x2 * c + x1 * sn;
    }
    {
        g_v[off_out]        = g_tv[off_in];
        g_v[off_out + HALF] = g_tv[off_in + HALF];
    }
}

// ---------------------------------------------------------------------------
// Row softmax over n=2048, one block (256 threads) per row; values stay in
// registers (8 per thread): one global read + one write.
// ---------------------------------------------------------------------------
__global__ __launch_bounds__(256)
void softmax_rows_kernel(float* __restrict__ p)
{
    const int n = S_;
    const long base = (long)blockIdx.x * n;
    const int tid = threadIdx.x;

    float v[8];
#pragma unroll
    for (int i = 0; i < 8; i++) v[i] = p[base + tid + i * 256];

    float m = v[0];
#pragma unroll
    for (int i = 1; i < 8; i++) m = fmaxf(m, v[i]);
#pragma unroll
    for (int o = 16; o; o >>= 1) m = fmaxf(m, __shfl_xor_sync(0xFFFFFFFFu, m, o));

    __shared__ float red[8];
    if ((tid & 31) == 0) red[tid >> 5] = m;
    __syncthreads();
    float bm = red[0];
#pragma unroll
    for (int i = 1; i < 8; i++) bm = fmaxf(bm, red[i]);
    __syncthreads();

    float s = 0.f;
#pragma unroll
    for (int i = 0; i < 8; i++) { v[i] = expf(v[i] - bm); s += v[i]; }
#pragma unroll
    for (int o = 16; o; o >>= 1) s += __shfl_xor_sync(0xFFFFFFFFu, s, o);
    if ((tid & 31) == 0) red[tid >> 5] = s;
    __syncthreads();
    float tot = 0.f;
#pragma unroll
    for (int i = 0; i < 8; i++) tot += red[i];
    const float rinv = 1.0f / tot;

#pragma unroll
    for (int i = 0; i < 8; i++) p[base + tid + i * 256] = v[i] * rinv;
}

// ---------------------------------------------------------------------------
// Launch
// ---------------------------------------------------------------------------
extern "C" void kernel_launch(void* const* d_in, const int* in_sizes, int n_in,
                              void* d_out, int out_size)
{
    const float* x  = (const float*)d_in[0];
    const float* qw = (const float*)d_in[1];
    const float* kw = (const float*)d_in[2];
    const float* vw = (const float*)d_in[3];
    const float* qb = (const float*)d_in[4];
    const float* kb = (const float*)d_in[5];
    const float* vb = (const float*)d_in[6];
    const float* ow = (const float*)d_in[7];
    const float* ob = (const float*)d_in[8];
    float* out = (float*)d_out;

    float *tq, *tk, *tv, *q, *k, *v, *sc, *ctx;
    cudaGetSymbolAddress((void**)&tq,  g_tq);
    cudaGetSymbolAddress((void**)&tk,  g_tk);
    cudaGetSymbolAddress((void**)&tv,  g_tv);
    cudaGetSymbolAddress((void**)&q,   g_q);
    cudaGetSymbolAddress((void**)&k,   g_k);
    cudaGetSymbolAddress((void**)&v,   g_v);
    cudaGetSymbolAddress((void**)&sc,  g_sc);
    cudaGetSymbolAddress((void**)&ctx, g_ctx);

    const dim3 blk(256);
    const float scaling = 0.08838834764831845f;   // 128^-0.5

    // 1-3: Q/K/V projections  (M=4096, N=2048, K=2048), C = x @ W^T + b
    {
        dim3 grid(D_ / BN, MROWS / BM, 1);
        sgemm_kernel<1><<<grid, blk>>>(x, qw, tq, MROWS, D_, D_,
                                       0, 0, 1, 0, 0, D_, qb, 1.0f);
        sgemm_kernel<1><<<grid, blk>>>(x, kw, tk, MROWS, D_, D_,
                                       0, 0, 1, 0, 0, D_, kb, 1.0f);
        sgemm_kernel<1><<<grid, blk>>>(x, vw, tv, MROWS, D_, D_,
                                       0, 0, 1, 0, 0, D_, vb, 1.0f);
    }

    // 4: RoPE (q,k) + permute (q,k,v) to [B,H,S,Dh]
    {
        const long total = (long)B_ * H_ * S_ * (DH / 2);   // 4,194,304
        dim3 grid((unsigned)((total + 255) / 256));
        rope_permute_kernel<<<grid, blk>>>();
    }

    // 5: scores = scale * Q @ K^T   (batched over B*H=32; M=N=2048, K=128)
    {
        dim3 grid(S_ / BN, S_ / BM, B_ * H_);
        sgemm_kernel<1><<<grid, blk>>>(q, k, sc, S_, S_, DH,
                                       (long)S_ * DH, (long)S_ * DH,
                                       1, (long)S_ * S_, 0, S_,
                                       nullptr, scaling);
    }

    // 6: softmax over last dim (65536 rows of 2048)
    softmax_rows_kernel<<<B_ * H_ * S_, blk>>>(sc);

    // 7: ctx = P @ V   (batched; M=2048, N=128, K=2048) -> [B,S,D] layout
    {
        dim3 grid(DH / BN, S_ / BM, B_ * H_);
        sgemm_kernel<0><<<grid, blk>>>(sc, v, ctx, S_, DH, S_,
                                       (long)S_ * S_, (long)S_ * DH,
                                       H_, (long)S_ * D_, (long)DH, D_,
                                       nullptr, 1.0f);
    }

    // 8: out = ctx @ out_w^T + out_b
    {
        dim3 grid(D_ / BN, MROWS / BM, 1);
        sgemm_kernel<1><<<grid, blk>>>(ctx, ow, out, MROWS, D_, D_,
                                       0, 0, 1, 0, 0, D_, ob, 1.0f);
    }
}

// round 4
// speedup vs baseline: 1.9290x; 1.9290x over previous
#include <cuda_runtime.h>
#include <cuda_fp16.h>
#include <cstdint>
#include <math.h>

// Problem constants
#define B_  2
#define S_  2048
#define D_  2048
#define H_  16
#define DH  128
#define MROWS (B_ * S_)          // 4096

// ---------------------------------------------------------------------------
// Scratch (static __device__ arrays; no allocation anywhere)
// ---------------------------------------------------------------------------
__device__ float g_tq[(size_t)MROWS * D_];
__device__ float g_tk[(size_t)MROWS * D_];
__device__ float g_tv[(size_t)MROWS * D_];
__device__ float g_sc[(size_t)B_ * H_ * S_ * S_];        // 537MB fp32 scores

__device__ __align__(256) __half g_xh [(size_t)MROWS * D_];
__device__ __align__(256) __half g_xl [(size_t)MROWS * D_];
__device__ __align__(256) __half g_qwh[(size_t)D_ * D_];
__device__ __align__(256) __half g_qwl[(size_t)D_ * D_];
__device__ __align__(256) __half g_kwh[(size_t)D_ * D_];
__device__ __align__(256) __half g_kwl[(size_t)D_ * D_];
__device__ __align__(256) __half g_vwh[(size_t)D_ * D_];
__device__ __align__(256) __half g_vwl[(size_t)D_ * D_];
__device__ __align__(256) __half g_owh[(size_t)D_ * D_];
__device__ __align__(256) __half g_owl[(size_t)D_ * D_];
__device__ __align__(256) __half g_qh [(size_t)B_ * H_ * S_ * DH];
__device__ __align__(256) __half g_ql [(size_t)B_ * H_ * S_ * DH];
__device__ __align__(256) __half g_kh [(size_t)B_ * H_ * S_ * DH];
__device__ __align__(256) __half g_kl [(size_t)B_ * H_ * S_ * DH];
__device__ __align__(256) __half g_vh [(size_t)B_ * H_ * S_ * DH];
__device__ __align__(256) __half g_vl [(size_t)B_ * H_ * S_ * DH];
__device__ __align__(256) __half g_sch[(size_t)B_ * H_ * S_ * S_];
__device__ __align__(256) __half g_scl[(size_t)B_ * H_ * S_ * S_];
__device__ __align__(256) __half g_ctxh[(size_t)MROWS * D_];
__device__ __align__(256) __half g_ctxl[(size_t)MROWS * D_];

// ---------------------------------------------------------------------------
// Helpers (all sm_80-era instructions: valid on base sm_103 target)
// ---------------------------------------------------------------------------
#define SWZ(x) ((x) ^ (((x) >> 3) & 0x70))

#define LDSM4(r, addr) \
    asm volatile("ldmatrix.sync.aligned.m8n8.x4.shared.b16 {%0,%1,%2,%3}, [%4];" \
        : "=r"((r)[0]), "=r"((r)[1]), "=r"((r)[2]), "=r"((r)[3]) : "r"(addr))

#define MMA(d, a, b0, b1) \
    asm volatile("mma.sync.aligned.m16n8k16.row.col.f32.f16.f16.f32 " \
        "{%0,%1,%2,%3},{%4,%5,%6,%7},{%8,%9},{%0,%1,%2,%3};" \
        : "+f"((d)[0]), "+f"((d)[1]), "+f"((d)[2]), "+f"((d)[3]) \
        : "r"((a)[0]), "r"((a)[1]), "r"((a)[2]), "r"((a)[3]), "r"(b0), "r"(b1))

#define CP16(dst, src) \
    asm volatile("cp.async.cg.shared.global [%0], [%1], 16;" :: "r"(dst), "l"(src))
#define CP_COMMIT() asm volatile("cp.async.commit_group;" ::: "memory")
#define CP_WAIT0()  asm volatile("cp.async.wait_group 0;"  ::: "memory")

__device__ __forceinline__ void split2(float x, __half& h, __half& l) {
    h = __float2half(x);
    l = __float2half(x - __half2float(h));
}

// ---------------------------------------------------------------------------
// fp16-split HMMA GEMM.  C = scale * (A @ op(B)) + bias
//   A:  [M,K] K-major fp16 (hi/lo), row stride == K
//   TRANSB=1: B [N,K] K-major fp16 hi/lo, row stride ldb  (C = A @ B^T)
//   TRANSB=0: B [K,N] row-major fp16 hi/lo, row stride ldb (C = A @ B)
//   SPLIT_OUT=0: C0 = fp32 out (+bias,*scale).  SPLIT_OUT=1: C0/C1 fp16 hi/lo.
// Block 128x128, BK=64 fp16; 8 warps of 64x32; cp.async double buffer.
// smem: 2 buffers x [Ah 16K | Al 16K | Bh 16K | Bl 16K] = 131072 B.
// ---------------------------------------------------------------------------
template <int TRANSB, int SPLIT_OUT>
__global__ __launch_bounds__(256, 1)
void gemm_hs(const __half* __restrict__ Ah, const __half* __restrict__ Al,
             const __half* __restrict__ Bh, const __half* __restrict__ Bl,
             void* __restrict__ C0, void* __restrict__ C1,
             int K, int ldb, long aB, long bB,
             int cDiv, long cS1, long cS2, int ldc,
             const float* __restrict__ bias, float scale)
{
    extern __shared__ char smem[];
    const uint32_t sb = (uint32_t)__cvta_generic_to_shared(smem);

    const int tid = threadIdx.x, wid = tid >> 5, lane = tid & 31;
    const long bm = (long)blockIdx.y * 128;
    const long bn = (long)blockIdx.x * 128;
    const int z = blockIdx.z;

    const __half* Agh = Ah + (long)z * aB;
    const __half* Agl = Al + (long)z * aB;
    const __half* Bgh = Bh + (long)z * bB;
    const __half* Bgl = Bl + (long)z * bB;
    const long coff = (long)(z / cDiv) * cS1 + (long)(z % cDiv) * cS2;

    // cp.async staging: thread -> (row, 4 consecutive 16B chunks)
    const int srow = tid >> 1;
    const int sc0  = (tid & 1) * 4;
    uint32_t soff[4];
#pragma unroll
    for (int i = 0; i < 4; i++)
        soff[i] = SWZ((uint32_t)(srow * 128 + (sc0 + i) * 16));

    // TRANSB==0 B staging: thread -> (k row, 32 n's)
    const int bk_  = tid >> 2;
    const int bn0_ = (tid & 3) * 32;
    uint4 brH[4], brL[4];

    const int nk = K / 64;

    // ---- prologue: stage buffer 0 (kt = 0) ----
    {
        const __half* pa = Agh + (bm + srow) * (long)K + sc0 * 8;
        const __half* pl = Agl + (bm + srow) * (long)K + sc0 * 8;
#pragma unroll
        for (int i = 0; i < 4; i++) {
            CP16(sb + soff[i],         pa + i * 8);
            CP16(sb + 16384 + soff[i], pl + i * 8);
        }
        if (TRANSB) {
            const __half* pb  = Bgh + (bn + srow) * (long)ldb + sc0 * 8;
            const __half* pbl = Bgl + (bn + srow) * (long)ldb + sc0 * 8;
#pragma unroll
            for (int i = 0; i < 4; i++) {
                CP16(sb + 32768 + soff[i], pb + i * 8);
                CP16(sb + 49152 + soff[i], pbl + i * 8);
            }
        }
        CP_COMMIT();
        if (!TRANSB) {
            const __half* pb  = Bgh + (long)bk_ * ldb + bn0_;
            const __half* pbl = Bgl + (long)bk_ * ldb + bn0_;
#pragma unroll
            for (int i = 0; i < 4; i++) {
                brH[i] = *(const uint4*)(pb + i * 8);
                brL[i] = *(const uint4*)(pbl + i * 8);
            }
#pragma unroll
            for (int i = 0; i < 4; i++) {
                const __half* hp = (const __half*)&brH[i];
                const __half* lp = (const __half*)&brL[i];
#pragma unroll
                for (int j = 0; j < 8; j++) {
                    uint32_t off = SWZ((uint32_t)((bn0_ + i * 8 + j) * 128 + bk_ * 2));
                    *(__half*)(smem + 32768 + off) = hp[j];
                    *(__half*)(smem + 49152 + off) = lp[j];
                }
            }
            if (nk > 1) {
                const __half* pb1  = Bgh + (long)(64 + bk_) * ldb + bn0_;
                const __half* pbl1 = Bgl + (long)(64 + bk_) * ldb + bn0_;
#pragma unroll
                for (int i = 0; i < 4; i++) {
                    brH[i] = *(const uint4*)(pb1 + i * 8);
                    brL[i] = *(const uint4*)(pbl1 + i * 8);
                }
            }
        }
    }

    float acc[4][4][4];
#pragma unroll
    for (int a = 0; a < 4; a++)
#pragma unroll
        for (int b = 0; b < 4; b++)
#pragma unroll
            for (int c = 0; c < 4; c++) acc[a][b][c] = 0.f;

    const int m0 = (wid & 1) * 64;
    const int n0 = (wid >> 1) * 32;
    // ldmatrix per-lane address params
    const int rA = lane & 15;
    const int cA = lane >> 4;                    // 0/1: k-halves
    const int rB = ((lane >> 1) & 8) + (lane & 7);
    const int cB = (lane >> 3) & 1;

    for (int kt = 0; kt < nk; ++kt) {
        const int s = kt & 1;
        CP_WAIT0();
        __syncthreads();

        if (kt + 1 < nk) {
            const int s2 = s ^ 1;
            const uint32_t db = sb + s2 * 65536;
            const __half* pa = Agh + (bm + srow) * (long)K + (kt + 1) * 64 + sc0 * 8;
            const __half* pl = Agl + (bm + srow) * (long)K + (kt + 1) * 64 + sc0 * 8;
#pragma unroll
            for (int i = 0; i < 4; i++) {
                CP16(db + soff[i],         pa + i * 8);
                CP16(db + 16384 + soff[i], pl + i * 8);
            }
            if (TRANSB) {
                const __half* pb  = Bgh + (bn + srow) * (long)ldb + (kt + 1) * 64 + sc0 * 8;
                const __half* pbl = Bgl + (bn + srow) * (long)ldb + (kt + 1) * 64 + sc0 * 8;
#pragma unroll
                for (int i = 0; i < 4; i++) {
                    CP16(db + 32768 + soff[i], pb + i * 8);
                    CP16(db + 49152 + soff[i], pbl + i * 8);
                }
            }
            CP_COMMIT();
            if (!TRANSB) {
                char* bb = smem + s2 * 65536;
#pragma unroll
                for (int i = 0; i < 4; i++) {
                    const __half* hp = (const __half*)&brH[i];
                    const __half* lp = (const __half*)&brL[i];
#pragma unroll
                    for (int j = 0; j < 8; j++) {
                        uint32_t off = SWZ((uint32_t)((bn0_ + i * 8 + j) * 128 + bk_ * 2));
                        *(__half*)(bb + 32768 + off) = hp[j];
                        *(__half*)(bb + 49152 + off) = lp[j];
                    }
                }
                if (kt + 2 < nk) {
                    const __half* pb  = Bgh + ((long)(kt + 2) * 64 + bk_) * ldb + bn0_;
                    const __half* pbl = Bgl + ((long)(kt + 2) * 64 + bk_) * ldb + bn0_;
#pragma unroll
                    for (int i = 0; i < 4; i++) {
                        brH[i] = *(const uint4*)(pb + i * 8);
                        brL[i] = *(const uint4*)(pbl + i * 8);
                    }
                }
            }
        }

        // ---- compute buffer s ----
        const uint32_t ba = sb + (uint32_t)s * 65536;
#pragma unroll
        for (int ks = 0; ks < 4; ks++) {
            uint32_t ah[4][4], al[4][4], bh[2][4], bl[2][4];
#pragma unroll
            for (int mt = 0; mt < 4; mt++) {
                const uint32_t addr = ba +
                    SWZ((uint32_t)((m0 + mt * 16 + rA) * 128 + (ks * 2 + cA) * 16));
                LDSM4(ah[mt], addr);
                LDSM4(al[mt], addr + 16384);
            }
#pragma unroll
            for (int p = 0; p < 2; p++) {
                const uint32_t addr = ba + 32768 +
                    SWZ((uint32_t)((n0 + p * 16 + rB) * 128 + (ks * 2 + cB) * 16));
                LDSM4(bh[p], addr);
                LDSM4(bl[p], addr + 16384);
            }
#pragma unroll
            for (int mt = 0; mt < 4; mt++)
#pragma unroll
                for (int nt = 0; nt < 4; nt++) {
                    const int p = nt >> 1, q = (nt & 1) * 2;
                    MMA(acc[mt][nt], ah[mt], bh[p][q], bh[p][q + 1]);
                    MMA(acc[mt][nt], ah[mt], bl[p][q], bl[p][q + 1]);
                    MMA(acc[mt][nt], al[mt], bh[p][q], bh[p][q + 1]);
                }
        }
    }

    // ---- epilogue ----
    const int g = lane >> 2, t = lane & 3;
#pragma unroll
    for (int mt = 0; mt < 4; mt++) {
        const long r0 = bm + m0 + mt * 16 + g;
#pragma unroll
        for (int nt = 0; nt < 4; nt++) {
            const long col = bn + n0 + nt * 8 + 2 * t;
            float c0 = acc[mt][nt][0] * scale, c1 = acc[mt][nt][1] * scale;
            float c2 = acc[mt][nt][2] * scale, c3 = acc[mt][nt][3] * scale;
            if (bias) {
                const float b0 = __ldg(bias + col), b1 = __ldg(bias + col + 1);
                c0 += b0; c1 += b1; c2 += b0; c3 += b1;
            }
            if (SPLIT_OUT) {
                __half* CH = (__half*)C0 + coff;
                __half* CL = (__half*)C1 + coff;
                __half h0, l0, h1, l1, h2, l2, h3, l3;
                split2(c0, h0, l0); split2(c1, h1, l1);
                split2(c2, h2, l2); split2(c3, h3, l3);
                __half2 hh01; hh01.x = h0; hh01.y = h1;
                __half2 ll01; ll01.x = l0; ll01.y = l1;
                __half2 hh23; hh23.x = h2; hh23.y = h3;
                __half2 ll23; ll23.x = l2; ll23.y = l3;
                *(__half2*)(CH + r0 * (long)ldc + col)       = hh01;
                *(__half2*)(CL + r0 * (long)ldc + col)       = ll01;
                *(__half2*)(CH + (r0 + 8) * (long)ldc + col) = hh23;
                *(__half2*)(CL + (r0 + 8) * (long)ldc + col) = ll23;
            } else {
                float* C = (float*)C0 + coff;
                *(float2*)(C + r0 * (long)ldc + col)       = make_float2(c0, c1);
                *(float2*)(C + (r0 + 8) * (long)ldc + col) = make_float2(c2, c3);
            }
        }
    }
}

// ---------------------------------------------------------------------------
// fp32 -> fp16 hi/lo split (elementwise, float4 vectorized)
// ---------------------------------------------------------------------------
__global__ __launch_bounds__(256)
void split_kernel(const float* __restrict__ in, __half* __restrict__ oh,
                  __half* __restrict__ ol, long n)
{
    const long i = ((long)blockIdx.x * blockDim.x + threadIdx.x) * 4;
    if (i >= n) return;
    float4 v = *(const float4*)(in + i);
    __half h0, l0, h1, l1, h2, l2, h3, l3;
    split2(v.x, h0, l0); split2(v.y, h1, l1);
    split2(v.z, h2, l2); split2(v.w, h3, l3);
    __half2 hh01; hh01.x = h0; hh01.y = h1;
    __half2 hh23; hh23.x = h2; hh23.y = h3;
    __half2 ll01; ll01.x = l0; ll01.y = l1;
    __half2 ll23; ll23.x = l2; ll23.y = l3;
    *(__half2*)(oh + i)     = hh01;
    *(__half2*)(oh + i + 2) = hh23;
    *(__half2*)(ol + i)     = ll01;
    *(__half2*)(ol + i + 2) = ll23;
}

// ---------------------------------------------------------------------------
// RoPE + permute [B,S,H,Dh] -> [B,H,S,Dh], output split fp16 hi/lo.
// v permute-only.
// ---------------------------------------------------------------------------
__global__ __launch_bounds__(256)
void rope_permute_kernel()
{
    const int HALF = DH / 2;
    long idx = (long)blockIdx.x * blockDim.x + threadIdx.x;
    const long total = (long)B_ * H_ * S_ * HALF;
    if (idx >= total) return;

    const int j = (int)(idx % HALF);
    const int s = (int)((idx / HALF) % S_);
    const int h = (int)((idx / ((long)HALF * S_)) % H_);
    const int b = (int)(idx / ((long)HALF * S_ * H_));

    const long off_in  = ((long)(b * S_ + s)) * D_ + h * DH + j;
    const long off_out = (((long)(b * H_ + h) * S_) + s) * DH + j;

    const float inv = expf(-(float)j * (9.210340371976184f / 64.0f)); // ln(10000)/64
    const float th  = (float)s * inv;
    const float c  = cosf(th);
    const float sn = sinf(th);

    {
        const float x1 = g_tq[off_in];
        const float x2 = g_tq[off_in + HALF];
        const float o1 = x1 * c - x2 * sn;
        const float o2 = x2 * c + x1 * sn;
        __half hh, hl;
        split2(o1, hh, hl); g_qh[off_out] = hh;        g_ql[off_out] = hl;
        split2(o2, hh, hl); g_qh[off_out + HALF] = hh; g_ql[off_out + HALF] = hl;
    }
    {
        const float x1 = g_tk[off_in];
        const float x2 = g_tk[off_in + HALF];
        const float o1 = x1 * c - x2 * sn;
        const float o2 = x2 * c + x1 * sn;
        __half hh, hl;
        split2(o1, hh, hl); g_kh[off_out] = hh;        g_kl[off_out] = hl;
        split2(o2, hh, hl); g_kh[off_out + HALF] = hh; g_kl[off_out + HALF] = hl;
    }
    {
        const float x1 = g_tv[off_in];
        const float x2 = g_tv[off_in + HALF];
        __half hh, hl;
        split2(x1, hh, hl); g_vh[off_out] = hh;        g_vl[off_out] = hl;
        split2(x2, hh, hl); g_vh[off_out + HALF] = hh; g_vl[off_out + HALF] = hl;
    }
}

// ---------------------------------------------------------------------------
// Row softmax over n=2048; output split fp16 hi/lo.
// ---------------------------------------------------------------------------
__global__ __launch_bounds__(256)
void softmax_rows_kernel(const float* __restrict__ p)
{
    const long base = (long)blockIdx.x * S_;
    const int tid = threadIdx.x;

    float v[8];
#pragma unroll
    for (int i = 0; i < 8; i++) v[i] = p[base + tid + i * 256];

    float m = v[0];
#pragma unroll
    for (int i = 1; i < 8; i++) m = fmaxf(m, v[i]);
#pragma unroll
    for (int o = 16; o; o >>= 1) m = fmaxf(m, __shfl_xor_sync(0xFFFFFFFFu, m, o));

    __shared__ float red[8];
    if ((tid & 31) == 0) red[tid >> 5] = m;
    __syncthreads();
    float bm = red[0];
#pragma unroll
    for (int i = 1; i < 8; i++) bm = fmaxf(bm, red[i]);
    __syncthreads();

    float s = 0.f;
#pragma unroll
    for (int i = 0; i < 8; i++) { v[i] = expf(v[i] - bm); s += v[i]; }
#pragma unroll
    for (int o = 16; o; o >>= 1) s += __shfl_xor_sync(0xFFFFFFFFu, s, o);
    if ((tid & 31) == 0) red[tid >> 5] = s;
    __syncthreads();
    float tot = 0.f;
#pragma unroll
    for (int i = 0; i < 8; i++) tot += red[i];
    const float rinv = 1.0f / tot;

#pragma unroll
    for (int i = 0; i < 8; i++) {
        const float pv = v[i] * rinv;
        __half hh, hl;
        split2(pv, hh, hl);
        g_sch[base + tid + i * 256] = hh;
        g_scl[base + tid + i * 256] = hl;
    }
}

// ---------------------------------------------------------------------------
// Launch
// ---------------------------------------------------------------------------
extern "C" void kernel_launch(void* const* d_in, const int* in_sizes, int n_in,
                              void* d_out, int out_size)
{
    const float* x  = (const float*)d_in[0];
    const float* qw = (const float*)d_in[1];
    const float* kw = (const float*)d_in[2];
    const float* vw = (const float*)d_in[3];
    const float* qb = (const float*)d_in[4];
    const float* kb = (const float*)d_in[5];
    const float* vb = (const float*)d_in[6];
    const float* ow = (const float*)d_in[7];
    const float* ob = (const float*)d_in[8];
    float* out = (float*)d_out;

    float *tq, *tk, *tv, *sc;
    __half *xh, *xl, *qwh, *qwl, *kwh, *kwl, *vwh, *vwl, *owh, *owl;
    __half *qh, *ql, *kh, *kl, *vh, *vl, *sch, *scl, *ctxh, *ctxl;
    cudaGetSymbolAddress((void**)&tq,  g_tq);
    cudaGetSymbolAddress((void**)&tk,  g_tk);
    cudaGetSymbolAddress((void**)&tv,  g_tv);
    cudaGetSymbolAddress((void**)&sc,  g_sc);
    cudaGetSymbolAddress((void**)&xh,  g_xh);
    cudaGetSymbolAddress((void**)&xl,  g_xl);
    cudaGetSymbolAddress((void**)&qwh, g_qwh);
    cudaGetSymbolAddress((void**)&qwl, g_qwl);
    cudaGetSymbolAddress((void**)&kwh, g_kwh);
    cudaGetSymbolAddress((void**)&kwl, g_kwl);
    cudaGetSymbolAddress((void**)&vwh, g_vwh);
    cudaGetSymbolAddress((void**)&vwl, g_vwl);
    cudaGetSymbolAddress((void**)&owh, g_owh);
    cudaGetSymbolAddress((void**)&owl, g_owl);
    cudaGetSymbolAddress((void**)&qh,  g_qh);
    cudaGetSymbolAddress((void**)&ql,  g_ql);
    cudaGetSymbolAddress((void**)&kh,  g_kh);
    cudaGetSymbolAddress((void**)&kl,  g_kl);
    cudaGetSymbolAddress((void**)&vh,  g_vh);
    cudaGetSymbolAddress((void**)&vl,  g_vl);
    cudaGetSymbolAddress((void**)&sch, g_sch);
    cudaGetSymbolAddress((void**)&scl, g_scl);
    cudaGetSymbolAddress((void**)&ctxh, g_ctxh);
    cudaGetSymbolAddress((void**)&ctxl, g_ctxl);

    const int SMEM = 131072;
    static bool attr_set = false;
    cudaFuncSetAttribute(gemm_hs<1, 0>, cudaFuncAttributeMaxDynamicSharedMemorySize, SMEM);
    cudaFuncSetAttribute(gemm_hs<0, 1>, cudaFuncAttributeMaxDynamicSharedMemorySize, SMEM);
    (void)attr_set;

    const dim3 blk(256);
    const float scaling = 0.08838834764831845f;   // 128^-0.5

    // 0: split fp32 inputs to fp16 hi/lo
    {
        const long nx = (long)MROWS * D_;
        const long nw = (long)D_ * D_;
        split_kernel<<<(unsigned)(nx / 4 / 256), blk>>>(x,  xh,  xl,  nx);
        split_kernel<<<(unsigned)(nw / 4 / 256), blk>>>(qw, qwh, qwl, nw);
        split_kernel<<<(unsigned)(nw / 4 / 256), blk>>>(kw, kwh, kwl, nw);
        split_kernel<<<(unsigned)(nw / 4 / 256), blk>>>(vw, vwh, vwl, nw);
        split_kernel<<<(unsigned)(nw / 4 / 256), blk>>>(ow, owh, owl, nw);
    }

    // 1-3: Q/K/V projections (M=4096, N=2048, K=2048), C = x @ W^T + b (fp32 out)
    {
        dim3 grid(D_ / 128, MROWS / 128, 1);
        gemm_hs<1, 0><<<grid, blk, SMEM>>>(xh, xl, qwh, qwl, tq, nullptr,
                                           D_, D_, 0, 0, 1, 0, 0, D_, qb, 1.0f);
        gemm_hs<1, 0><<<grid, blk, SMEM>>>(xh, xl, kwh, kwl, tk, nullptr,
                                           D_, D_, 0, 0, 1, 0, 0, D_, kb, 1.0f);
        gemm_hs<1, 0><<<grid, blk, SMEM>>>(xh, xl, vwh, vwl, tv, nullptr,
                                           D_, D_, 0, 0, 1, 0, 0, D_, vb, 1.0f);
    }

    // 4: RoPE (q,k) + permute to [B,H,S,Dh], split fp16 outputs
    {
        const long total = (long)B_ * H_ * S_ * (DH / 2);
        rope_permute_kernel<<<(unsigned)((total + 255) / 256), blk>>>();
    }

    // 5: scores = scale * Q @ K^T  (batched B*H=32; M=N=2048, K=128) -> fp32
    {
        dim3 grid(S_ / 128, S_ / 128, B_ * H_);
        gemm_hs<1, 0><<<grid, blk, SMEM>>>(qh, ql, kh, kl, sc, nullptr,
                                           DH, DH, (long)S_ * DH, (long)S_ * DH,
                                           1, (long)S_ * S_, 0, S_,
                                           nullptr, scaling);
    }

    // 6: softmax (65536 rows of 2048) -> split fp16 probs
    softmax_rows_kernel<<<B_ * H_ * S_, blk>>>(sc);

    // 7: ctx = P @ V  (batched; M=2048, N=128, K=2048) -> [B,S,D] fp16 hi/lo
    {
        dim3 grid(1, S_ / 128, B_ * H_);
        gemm_hs<0, 1><<<grid, blk, SMEM>>>(sch, scl, vh, vl, ctxh, ctxl,
                                           S_, DH, (long)S_ * S_, (long)S_ * DH,
                                           H_, (long)S_ * D_, (long)DH, D_,
                                           nullptr, 1.0f);
    }

    // 8: out = ctx @ out_w^T + out_b (fp32 out)
    {
        dim3 grid(D_ / 128, MROWS / 128, 1);
        gemm_hs<1, 0><<<grid, blk, SMEM>>>(ctxh, ctxl, owh, owl, out, nullptr,
                                           D_, D_, 0, 0, 1, 0, 0, D_, ob, 1.0f);
    }
}

// round 6
// speedup vs baseline: 2.2711x; 1.1773x over previous
#include <cuda_runtime.h>
#include <cuda_fp16.h>
#include <cstdint>
#include <math.h>

// Problem constants
#define B_  2
#define S_  2048
#define D_  2048
#define H_  16
#define DH  128
#define MROWS (B_ * S_)          // 4096

// ---------------------------------------------------------------------------
// Scratch (static __device__ arrays; no allocation anywhere)
// ---------------------------------------------------------------------------
__device__ float g_tq[(size_t)MROWS * D_];
__device__ float g_tk[(size_t)MROWS * D_];
__device__ float g_tv[(size_t)MROWS * D_];

__device__ __align__(256) __half g_xh [(size_t)MROWS * D_];
__device__ __align__(256) __half g_xl [(size_t)MROWS * D_];
__device__ __align__(256) __half g_qwh[(size_t)D_ * D_];
__device__ __align__(256) __half g_qwl[(size_t)D_ * D_];
__device__ __align__(256) __half g_kwh[(size_t)D_ * D_];
__device__ __align__(256) __half g_kwl[(size_t)D_ * D_];
__device__ __align__(256) __half g_vwh[(size_t)D_ * D_];
__device__ __align__(256) __half g_vwl[(size_t)D_ * D_];
__device__ __align__(256) __half g_owh[(size_t)D_ * D_];
__device__ __align__(256) __half g_owl[(size_t)D_ * D_];
__device__ __align__(256) __half g_qh [(size_t)B_ * H_ * S_ * DH];
__device__ __align__(256) __half g_ql [(size_t)B_ * H_ * S_ * DH];
__device__ __align__(256) __half g_kh [(size_t)B_ * H_ * S_ * DH];
__device__ __align__(256) __half g_kl [(size_t)B_ * H_ * S_ * DH];
__device__ __align__(256) __half g_vth[(size_t)B_ * H_ * DH * S_];   // V^T [B,H,Dh,S]
__device__ __align__(256) __half g_vtl[(size_t)B_ * H_ * DH * S_];
__device__ __align__(256) __half g_ctxh[(size_t)MROWS * D_];
__device__ __align__(256) __half g_ctxl[(size_t)MROWS * D_];

// ---------------------------------------------------------------------------
// Helpers (all sm_80-era instructions: valid on base sm_103 target)
// ---------------------------------------------------------------------------
#define SWZ(x) ((x) ^ (((x) >> 3) & 0x70))

#define LDSM4(r, addr) \
    asm volatile("ldmatrix.sync.aligned.m8n8.x4.shared.b16 {%0,%1,%2,%3}, [%4];" \
        : "=r"((r)[0]), "=r"((r)[1]), "=r"((r)[2]), "=r"((r)[3]) : "r"(addr))

#define MMA(d, a, b0, b1) \
    asm volatile("mma.sync.aligned.m16n8k16.row.col.f32.f16.f16.f32 " \
        "{%0,%1,%2,%3},{%4,%5,%6,%7},{%8,%9},{%0,%1,%2,%3};" \
        : "+f"((d)[0]), "+f"((d)[1]), "+f"((d)[2]), "+f"((d)[3]) \
        : "r"((a)[0]), "r"((a)[1]), "r"((a)[2]), "r"((a)[3]), "r"(b0), "r"(b1))

#define CP16(dst, src) \
    asm volatile("cp.async.cg.shared.global [%0], [%1], 16;" :: "r"(dst), "l"(src))
#define CP_COMMIT() asm volatile("cp.async.commit_group;" ::: "memory")
#define CP_WAIT0()  asm volatile("cp.async.wait_group 0;"  ::: "memory")

__device__ __forceinline__ void split2(float x, __half& h, __half& l) {
    h = __float2half(x);
    l = __float2half(x - __half2float(h));
}
__device__ __forceinline__ uint32_t packh2(__half a, __half b) {
    __half2 t; t.x = a; t.y = b;
    return *(uint32_t*)&t;
}

// ---------------------------------------------------------------------------
// fp16-split HMMA GEMM (R4-validated).  C = scale * (A @ B^T) + bias, fp32 out
//   A [M,K] K-major fp16 hi/lo, row stride K; B [N,K] K-major, row stride ldb.
// Block 128x128, BK=64; 8 warps of 64x32; cp.async double buffer.
// ---------------------------------------------------------------------------
__global__ __launch_bounds__(256, 1)
void gemm_hs(const __half* __restrict__ Ah, const __half* __restrict__ Al,
             const __half* __restrict__ Bh, const __half* __restrict__ Bl,
             float* __restrict__ C, int K, int ldb,
             const float* __restrict__ bias, float scale)
{
    extern __shared__ char smem[];
    const uint32_t sb = (uint32_t)__cvta_generic_to_shared(smem);

    const int tid = threadIdx.x, wid = tid >> 5, lane = tid & 31;
    const long bm = (long)blockIdx.y * 128;
    const long bn = (long)blockIdx.x * 128;

    const int srow = tid >> 1;
    const int sc0  = (tid & 1) * 4;
    uint32_t soff[4];
#pragma unroll
    for (int i = 0; i < 4; i++)
        soff[i] = SWZ((uint32_t)(srow * 128 + (sc0 + i) * 16));

    const int nk = K / 64;

    // prologue: stage buffer 0
    {
        const __half* pa = Ah + (bm + srow) * (long)K + sc0 * 8;
        const __half* pl = Al + (bm + srow) * (long)K + sc0 * 8;
        const __half* pb  = Bh + (bn + srow) * (long)ldb + sc0 * 8;
        const __half* pbl = Bl + (bn + srow) * (long)ldb + sc0 * 8;
#pragma unroll
        for (int i = 0; i < 4; i++) {
            CP16(sb + soff[i],         pa + i * 8);
            CP16(sb + 16384 + soff[i], pl + i * 8);
            CP16(sb + 32768 + soff[i], pb + i * 8);
            CP16(sb + 49152 + soff[i], pbl + i * 8);
        }
        CP_COMMIT();
    }

    float acc[4][4][4];
#pragma unroll
    for (int a = 0; a < 4; a++)
#pragma unroll
        for (int b = 0; b < 4; b++)
#pragma unroll
            for (int c = 0; c < 4; c++) acc[a][b][c] = 0.f;

    const int m0 = (wid & 1) * 64;
    const int n0 = (wid >> 1) * 32;
    const int rA = lane & 15;
    const int cA = lane >> 4;
    const int rB = ((lane >> 1) & 8) + (lane & 7);
    const int cB = (lane >> 3) & 1;

    for (int kt = 0; kt < nk; ++kt) {
        const int s = kt & 1;
        CP_WAIT0();
        __syncthreads();

        if (kt + 1 < nk) {
            const uint32_t db = sb + (s ^ 1) * 65536;
            const __half* pa = Ah + (bm + srow) * (long)K + (kt + 1) * 64 + sc0 * 8;
            const __half* pl = Al + (bm + srow) * (long)K + (kt + 1) * 64 + sc0 * 8;
            const __half* pb  = Bh + (bn + srow) * (long)ldb + (kt + 1) * 64 + sc0 * 8;
            const __half* pbl = Bl + (bn + srow) * (long)ldb + (kt + 1) * 64 + sc0 * 8;
#pragma unroll
            for (int i = 0; i < 4; i++) {
                CP16(db + soff[i],         pa + i * 8);
                CP16(db + 16384 + soff[i], pl + i * 8);
                CP16(db + 32768 + soff[i], pb + i * 8);
                CP16(db + 49152 + soff[i], pbl + i * 8);
            }
            CP_COMMIT();
        }

        const uint32_t ba = sb + (uint32_t)s * 65536;
#pragma unroll
        for (int ks = 0; ks < 4; ks++) {
            uint32_t ah[4][4], al[4][4], bh[2][4], bl[2][4];
#pragma unroll
            for (int mt = 0; mt < 4; mt++) {
                const uint32_t addr = ba +
                    SWZ((uint32_t)((m0 + mt * 16 + rA) * 128 + (ks * 2 + cA) * 16));
                LDSM4(ah[mt], addr);
                LDSM4(al[mt], addr + 16384);
            }
#pragma unroll
            for (int p = 0; p < 2; p++) {
                const uint32_t addr = ba + 32768 +
                    SWZ((uint32_t)((n0 + p * 16 + rB) * 128 + (ks * 2 + cB) * 16));
                LDSM4(bh[p], addr);
                LDSM4(bl[p], addr + 16384);
            }
#pragma unroll
            for (int mt = 0; mt < 4; mt++)
#pragma unroll
                for (int nt = 0; nt < 4; nt++) {
                    const int p = nt >> 1, q = (nt & 1) * 2;
                    MMA(acc[mt][nt], ah[mt], bh[p][q], bh[p][q + 1]);
                    MMA(acc[mt][nt], ah[mt], bl[p][q], bl[p][q + 1]);
                    MMA(acc[mt][nt], al[mt], bh[p][q], bh[p][q + 1]);
                }
        }
    }

    const int g = lane >> 2, t = lane & 3;
#pragma unroll
    for (int mt = 0; mt < 4; mt++) {
        const long r0 = bm + m0 + mt * 16 + g;
#pragma unroll
        for (int nt = 0; nt < 4; nt++) {
            const long col = bn + n0 + nt * 8 + 2 * t;
            float c0 = acc[mt][nt][0] * scale, c1 = acc[mt][nt][1] * scale;
            float c2 = acc[mt][nt][2] * scale, c3 = acc[mt][nt][3] * scale;
            if (bias) {
                const float b0 = __ldg(bias + col), b1 = __ldg(bias + col + 1);
                c0 += b0; c1 += b1; c2 += b0; c3 += b1;
            }
            *(float2*)(C + r0 * (long)D_ + col)       = make_float2(c0, c1);
            *(float2*)(C + (r0 + 8) * (long)D_ + col) = make_float2(c2, c3);
        }
    }
}

// ---------------------------------------------------------------------------
// Flash attention: per CTA = 128 Q rows x one (b,h).
// Q (hi/lo) resident in smem; K and V^T streamed in 64-seq chunks, double
// buffered. S in registers; online softmax (exp2; scaling*log2e folded into
// q); P split hi/lo in registers feeds PV directly. Output: ctx split fp16
// hi/lo in [B,S,D] layout.
// smem: Q 64K | Kbuf 2x32K | Vbuf 2x32K = 192K.
// ---------------------------------------------------------------------------
#define NKV (S_ / 64)     // 32 chunks

__global__ __launch_bounds__(256, 1)
void flash_kernel(const __half* __restrict__ Qh, const __half* __restrict__ Ql,
                  const __half* __restrict__ Kh, const __half* __restrict__ Kl,
                  const __half* __restrict__ Vth, const __half* __restrict__ Vtl,
                  __half* __restrict__ Ch, __half* __restrict__ Cl)
{
    extern __shared__ char smem[];
    const uint32_t sb = (uint32_t)__cvta_generic_to_shared(smem);

    const int tid = threadIdx.x, wid = tid >> 5, lane = tid & 31;
    const int qt = blockIdx.x;       // q tile (16)
    const int bh = blockIdx.y;       // b*H + h (32)
    const int b  = bh >> 4, h = bh & 15;

    const __half* Qhp = Qh + ((long)bh * S_ + (long)qt * 128) * DH;
    const __half* Qlp = Ql + ((long)bh * S_ + (long)qt * 128) * DH;
    const __half* Khp = Kh + (long)bh * S_ * DH;
    const __half* Klp = Kl + (long)bh * S_ * DH;
    const __half* Vhp = Vth + (long)bh * DH * S_;
    const __half* Vlp = Vtl + (long)bh * DH * S_;

    // smem layout (byte offsets from sb):
    //  Q hi: [0, 16384) Dh0-63, [16384, 32768) Dh64-127 ; Q lo at +32768
    //  K buf s: 65536 + s*32768: KH0 8K | KH1 8K | KL0 8K | KL1 8K
    //  V buf s: 131072 + s*32768: VH 16K | VL 16K
    const uint32_t KBUF0 = 65536, VBUF0 = 131072;

    // ---- prologue: stage Q (16 cp per thread) ----
    {
        const int r = tid >> 1, c0 = (tid & 1) * 8;
        const __half* s1 = Qhp + (long)r * DH;
        const __half* s2 = Qlp + (long)r * DH;
#pragma unroll
        for (int j = 0; j < 8; j++) {
            const int c = c0 + j;
            const uint32_t d = sb + ((c >= 8) ? 16384u : 0u) +
                               SWZ((uint32_t)(r * 128 + (c & 7) * 16));
            CP16(d,          s1 + c * 8);
            CP16(d + 32768u, s2 + c * 8);
        }
    }
    // ---- stage KV chunk `it` into buffer base (k/v dst) ----
    auto stageKV = [&](int it, uint32_t kdst, uint32_t vdst) {
        {
            const int r = tid >> 2, c0 = (tid & 3) * 4;
            const __half* s1 = Khp + ((long)it * 64 + r) * DH;
            const __half* s2 = Klp + ((long)it * 64 + r) * DH;
#pragma unroll
            for (int j = 0; j < 4; j++) {
                const int c = c0 + j;
                const uint32_t d = kdst + ((c >= 8) ? 8192u : 0u) +
                                   SWZ((uint32_t)(r * 128 + (c & 7) * 16));
                CP16(d,          s1 + c * 8);
                CP16(d + 16384u, s2 + c * 8);
            }
        }
        {
            const int dd = tid >> 1, c0 = (tid & 1) * 4;
            const __half* s1 = Vhp + (long)dd * S_ + it * 64;
            const __half* s2 = Vlp + (long)dd * S_ + it * 64;
#pragma unroll
            for (int j = 0; j < 4; j++) {
                const int c = c0 + j;
                const uint32_t d = vdst + SWZ((uint32_t)(dd * 128 + c * 16));
                CP16(d,          s1 + c * 8);
                CP16(d + 16384u, s2 + c * 8);
            }
        }
    };
    stageKV(0, sb + KBUF0, sb + VBUF0);
    CP_COMMIT();

    const int wm = wid * 16;                 // warp's 16 q-rows
    const int rA = lane & 15;
    const int cA = lane >> 4;
    const int rB = ((lane >> 1) & 8) + (lane & 7);
    const int cB = (lane >> 3) & 1;
    const int g = lane >> 2, t = lane & 3;

    float o[16][4];
#pragma unroll
    for (int i = 0; i < 16; i++)
#pragma unroll
        for (int j = 0; j < 4; j++) o[i][j] = 0.f;
    float m0 = -INFINITY, m1 = -INFINITY, l0 = 0.f, l1 = 0.f;

    for (int it = 0; it < NKV; ++it) {
        const int s = it & 1;
        CP_WAIT0();
        __syncthreads();
        if (it + 1 < NKV) {
            const int s2 = s ^ 1;
            stageKV(it + 1, sb + KBUF0 + s2 * 32768u, sb + VBUF0 + s2 * 32768u);
            CP_COMMIT();
        }

        const uint32_t kbuf = sb + KBUF0 + (uint32_t)s * 32768u;
        const uint32_t vbuf = sb + VBUF0 + (uint32_t)s * 32768u;

        // ---- S = Q' K^T  (128x64 per CTA, 16x64 per warp) ----
        float sa[8][4];
#pragma unroll
        for (int i = 0; i < 8; i++)
#pragma unroll
            for (int j = 0; j < 4; j++) sa[i][j] = 0.f;

#pragma unroll
        for (int ks = 0; ks < 8; ks++) {
            uint32_t ah[4], al[4], bh[4][4], bl[4][4];
            const uint32_t qa = sb + (ks >> 2) * 16384u +
                SWZ((uint32_t)((wm + rA) * 128 + ((ks & 3) * 2 + cA) * 16));
            LDSM4(ah, qa);
            LDSM4(al, qa + 32768u);
            const uint32_t kb2 = kbuf + (ks >> 2) * 8192u;
#pragma unroll
            for (int p = 0; p < 4; p++) {
                const uint32_t addr = kb2 +
                    SWZ((uint32_t)((p * 16 + rB) * 128 + ((ks & 3) * 2 + cB) * 16));
                LDSM4(bh[p], addr);
                LDSM4(bl[p], addr + 16384u);
            }
#pragma unroll
            for (int nt = 0; nt < 8; nt++) {
                const int p = nt >> 1, q = (nt & 1) * 2;
                MMA(sa[nt], ah, bh[p][q], bh[p][q + 1]);
                MMA(sa[nt], ah, bl[p][q], bl[p][q + 1]);
                MMA(sa[nt], al, bh[p][q], bh[p][q + 1]);
            }
        }

        // ---- online softmax (rows g and g+8) ----
        float nm0 = sa[0][0], nm1 = sa[0][2];
#pragma unroll
        for (int nt = 0; nt < 8; nt++) {
            nm0 = fmaxf(nm0, fmaxf(sa[nt][0], sa[nt][1]));
            nm1 = fmaxf(nm1, fmaxf(sa[nt][2], sa[nt][3]));
        }
        nm0 = fmaxf(nm0, __shfl_xor_sync(0xFFFFFFFFu, nm0, 1));
        nm0 = fmaxf(nm0, __shfl_xor_sync(0xFFFFFFFFu, nm0, 2));
        nm1 = fmaxf(nm1, __shfl_xor_sync(0xFFFFFFFFu, nm1, 1));
        nm1 = fmaxf(nm1, __shfl_xor_sync(0xFFFFFFFFu, nm1, 2));

        const float mn0 = fmaxf(m0, nm0), mn1 = fmaxf(m1, nm1);
        const float al0 = exp2f(m0 - mn0), al1 = exp2f(m1 - mn1);
        m0 = mn0; m1 = mn1;

        float rs0 = 0.f, rs1 = 0.f;
#pragma unroll
        for (int nt = 0; nt < 8; nt++) {
            sa[nt][0] = exp2f(sa[nt][0] - m0);
            sa[nt][1] = exp2f(sa[nt][1] - m0);
            sa[nt][2] = exp2f(sa[nt][2] - m1);
            sa[nt][3] = exp2f(sa[nt][3] - m1);
            rs0 += sa[nt][0] + sa[nt][1];
            rs1 += sa[nt][2] + sa[nt][3];
        }
        rs0 += __shfl_xor_sync(0xFFFFFFFFu, rs0, 1);
        rs0 += __shfl_xor_sync(0xFFFFFFFFu, rs0, 2);
        rs1 += __shfl_xor_sync(0xFFFFFFFFu, rs1, 1);
        rs1 += __shfl_xor_sync(0xFFFFFFFFu, rs1, 2);
        l0 = l0 * al0 + rs0;
        l1 = l1 * al1 + rs1;

#pragma unroll
        for (int nt = 0; nt < 16; nt++) {
            o[nt][0] *= al0; o[nt][1] *= al0;
            o[nt][2] *= al1; o[nt][3] *= al1;
        }

        // ---- O += P V   (P[16x64] from registers, V^T from smem) ----
#pragma unroll
        for (int kb = 0; kb < 4; kb++) {
            // pack P hi/lo A-fragments for this k-block of 16
            uint32_t aPh[4], aPl[4];
            {
                const float p00 = sa[2 * kb][0],     p01 = sa[2 * kb][1];
                const float p10 = sa[2 * kb][2],     p11 = sa[2 * kb][3];
                const float q00 = sa[2 * kb + 1][0], q01 = sa[2 * kb + 1][1];
                const float q10 = sa[2 * kb + 1][2], q11 = sa[2 * kb + 1][3];
                __half hA, lA, hB, lB;
                split2(p00, hA, lA); split2(p01, hB, lB);
                aPh[0] = packh2(hA, hB); aPl[0] = packh2(lA, lB);
                split2(p10, hA, lA); split2(p11, hB, lB);
                aPh[1] = packh2(hA, hB); aPl[1] = packh2(lA, lB);
                split2(q00, hA, lA); split2(q01, hB, lB);
                aPh[2] = packh2(hA, hB); aPl[2] = packh2(lA, lB);
                split2(q10, hA, lA); split2(q11, hB, lB);
                aPh[3] = packh2(hA, hB); aPl[3] = packh2(lA, lB);
            }
#pragma unroll
            for (int pp = 0; pp < 8; pp++) {
                uint32_t vb[4], vbl[4];
                const uint32_t addr = vbuf +
                    SWZ((uint32_t)((pp * 16 + rB) * 128 + (kb * 2 + cB) * 16));
                LDSM4(vb, addr);
                LDSM4(vbl, addr + 16384u);
                MMA(o[pp * 2],     aPh, vb[0],  vb[1]);
                MMA(o[pp * 2],     aPh, vbl[0], vbl[1]);
                MMA(o[pp * 2],     aPl, vb[0],  vb[1]);
                MMA(o[pp * 2 + 1], aPh, vb[2],  vb[3]);
                MMA(o[pp * 2 + 1], aPh, vbl[2], vbl[3]);
                MMA(o[pp * 2 + 1], aPl, vb[2],  vb[3]);
            }
        }
    }

    // ---- epilogue: normalize, split, store [B,S,D] ----
    const float r0i = 1.0f / l0, r1i = 1.0f / l1;
    const long row0 = (long)b * S_ + (long)qt * 128 + wm + g;
    const long row1 = row0 + 8;
#pragma unroll
    for (int nt = 0; nt < 16; nt++) {
        const long col = (long)h * DH + nt * 8 + 2 * t;
        const float c00 = o[nt][0] * r0i, c01 = o[nt][1] * r0i;
        const float c10 = o[nt][2] * r1i, c11 = o[nt][3] * r1i;
        __half hA, lA, hB, lB;
        split2(c00, hA, lA); split2(c01, hB, lB);
        *(uint32_t*)(Ch + row0 * D_ + col) = packh2(hA, hB);
        *(uint32_t*)(Cl + row0 * D_ + col) = packh2(lA, lB);
        split2(c10, hA, lA); split2(c11, hB, lB);
        *(uint32_t*)(Ch + row1 * D_ + col) = packh2(hA, hB);
        *(uint32_t*)(Cl + row1 * D_ + col) = packh2(lA, lB);
    }
}

// ---------------------------------------------------------------------------
// fp32 -> fp16 hi/lo split (elementwise, float4 vectorized)
// ---------------------------------------------------------------------------
__global__ __launch_bounds__(256)
void split_kernel(const float* __restrict__ in, __half* __restrict__ oh,
                  __half* __restrict__ ol, long n)
{
    const long i = ((long)blockIdx.x * blockDim.x + threadIdx.x) * 4;
    if (i >= n) return;
    float4 v = *(const float4*)(in + i);
    __half h0, l0, h1, l1, h2, l2, h3, l3;
    split2(v.x, h0, l0); split2(v.y, h1, l1);
    split2(v.z, h2, l2); split2(v.w, h3, l3);
    *(uint32_t*)(oh + i)     = packh2(h0, h1);
    *(uint32_t*)(oh + i + 2) = packh2(h2, h3);
    *(uint32_t*)(ol + i)     = packh2(l0, l1);
    *(uint32_t*)(ol + i + 2) = packh2(l2, l3);
}

// ---------------------------------------------------------------------------
// RoPE + permute [B,S,H,Dh] -> [B,H,S,Dh], split fp16 hi/lo.
// q additionally scaled by scaling*log2(e) (folded softmax scale).
// ---------------------------------------------------------------------------
__global__ __launch_bounds__(256)
void rope_permute_kernel()
{
    const int HALF = DH / 2;
    long idx = (long)blockIdx.x * blockDim.x + threadIdx.x;
    const long total = (long)B_ * H_ * S_ * HALF;
    if (idx >= total) return;

    const int j = (int)(idx % HALF);
    const int s = (int)((idx / HALF) % S_);
    const int h = (int)((idx / ((long)HALF * S_)) % H_);
    const int b = (int)(idx / ((long)HALF * S_ * H_));

    const long off_in  = ((long)(b * S_ + s)) * D_ + h * DH + j;
    const long off_out = (((long)(b * H_ + h) * S_) + s) * DH + j;

    const float inv = expf(-(float)j * (9.210340371976184f / 64.0f)); // ln(1e4)/64
    const float th  = (float)s * inv;
    const float c  = cosf(th);
    const float sn = sinf(th);

    const float QS = 0.08838834764831845f * 1.4426950408889634f; // scale*log2e

    {
        const float x1 = g_tq[off_in];
        const float x2 = g_tq[off_in + HALF];
        const float o1 = (x1 * c - x2 * sn) * QS;
        const float o2 = (x2 * c + x1 * sn) * QS;
        __half hh, hl;
        split2(o1, hh, hl); g_qh[off_out] = hh;        g_ql[off_out] = hl;
        split2(o2, hh, hl); g_qh[off_out + HALF] = hh; g_ql[off_out + HALF] = hl;
    }
    {
        const float x1 = g_tk[off_in];
        const float x2 = g_tk[off_in + HALF];
        const float o1 = x1 * c - x2 * sn;
        const float o2 = x2 * c + x1 * sn;
        __half hh, hl;
        split2(o1, hh, hl); g_kh[off_out] = hh;        g_kl[off_out] = hl;
        split2(o2, hh, hl); g_kh[off_out + HALF] = hh; g_kl[off_out + HALF] = hl;
    }
}

// ---------------------------------------------------------------------------
// V transpose: [B,S,H*Dh] fp32 -> [B,H,Dh,S] split fp16 hi/lo.
// 32x32 tiles via smem; block (32,8), grid (S/32, Dh/32, B*H).
// ---------------------------------------------------------------------------
__global__ __launch_bounds__(256)
void vtrans_kernel()
{
    __shared__ float tile[32][33];
    const int b = blockIdx.z >> 4, h = blockIdx.z & 15;
    const int s0 = blockIdx.x * 32, d0 = blockIdx.y * 32;

#pragma unroll
    for (int r = 0; r < 4; r++) {
        const int s = s0 + threadIdx.y + r * 8;
        tile[threadIdx.y + r * 8][threadIdx.x] =
            g_tv[((long)b * S_ + s) * D_ + h * DH + d0 + threadIdx.x];
    }
    __syncthreads();

#pragma unroll
    for (int r = 0; r < 4; r++) {
        const int d = d0 + threadIdx.y + r * 8;
        const float v = tile[threadIdx.x][threadIdx.y + r * 8];
        __half hh, hl;
        split2(v, hh, hl);
        const long off = ((long)blockIdx.z * DH + d) * S_ + s0 + threadIdx.x;
        g_vth[off] = hh;
        g_vtl[off] = hl;
    }
}

// ---------------------------------------------------------------------------
// Launch
// ---------------------------------------------------------------------------
extern "C" void kernel_launch(void* const* d_in, const int* in_sizes, int n_in,
                              void* d_out, int out_size)
{
    const float* x  = (const float*)d_in[0];
    const float* qw = (const float*)d_in[1];
    const float* kw = (const float*)d_in[2];
    const float* vw = (const float*)d_in[3];
    const float* qb = (const float*)d_in[4];
    const float* kb = (const float*)d_in[5];
    const float* vb = (const float*)d_in[6];
    const float* ow = (const float*)d_in[7];
    const float* ob = (const float*)d_in[8];
    float* out = (float*)d_out;

    float *tq, *tk, *tv;
    __half *xh, *xl, *qwh, *qwl, *kwh, *kwl, *vwh, *vwl, *owh, *owl;
    __half *qh, *ql, *kh, *kl, *vth, *vtl, *ctxh, *ctxl;
    cudaGetSymbolAddress((void**)&tq,  g_tq);
    cudaGetSymbolAddress((void**)&tk,  g_tk);
    cudaGetSymbolAddress((void**)&tv,  g_tv);
    cudaGetSymbolAddress((void**)&xh,  g_xh);
    cudaGetSymbolAddress((void**)&xl,  g_xl);
    cudaGetSymbolAddress((void**)&qwh, g_qwh);
    cudaGetSymbolAddress((void**)&qwl, g_qwl);
    cudaGetSymbolAddress((void**)&kwh, g_kwh);
    cudaGetSymbolAddress((void**)&kwl, g_kwl);
    cudaGetSymbolAddress((void**)&vwh, g_vwh);
    cudaGetSymbolAddress((void**)&vwl, g_vwl);
    cudaGetSymbolAddress((void**)&owh, g_owh);
    cudaGetSymbolAddress((void**)&owl, g_owl);
    cudaGetSymbolAddress((void**)&qh,  g_qh);
    cudaGetSymbolAddress((void**)&ql,  g_ql);
    cudaGetSymbolAddress((void**)&kh,  g_kh);
    cudaGetSymbolAddress((void**)&kl,  g_kl);
    cudaGetSymbolAddress((void**)&vth, g_vth);
    cudaGetSymbolAddress((void**)&vtl, g_vtl);
    cudaGetSymbolAddress((void**)&ctxh, g_ctxh);
    cudaGetSymbolAddress((void**)&ctxl, g_ctxl);

    const int SMEM_G = 131072;
    const int SMEM_F = 196608;
    cudaFuncSetAttribute(gemm_hs,     cudaFuncAttributeMaxDynamicSharedMemorySize, SMEM_G);
    cudaFuncSetAttribute(flash_kernel, cudaFuncAttributeMaxDynamicSharedMemorySize, SMEM_F);

    const dim3 blk(256);

    // 0: split fp32 inputs to fp16 hi/lo
    {
        const long nx = (long)MROWS * D_;
        const long nw = (long)D_ * D_;
        split_kernel<<<(unsigned)(nx / 4 / 256), blk>>>(x,  xh,  xl,  nx);
        split_kernel<<<(unsigned)(nw / 4 / 256), blk>>>(qw, qwh, qwl, nw);
        split_kernel<<<(unsigned)(nw / 4 / 256), blk>>>(kw, kwh, kwl, nw);
        split_kernel<<<(unsigned)(nw / 4 / 256), blk>>>(vw, vwh, vwl, nw);
        split_kernel<<<(unsigned)(nw / 4 / 256), blk>>>(ow, owh, owl, nw);
    }

    // 1-3: Q/K/V projections (M=4096, N=2048, K=2048), fp32 out
    {
        dim3 grid(D_ / 128, MROWS / 128, 1);
        gemm_hs<<<grid, blk, SMEM_G>>>(xh, xl, qwh, qwl, tq, D_, D_, qb, 1.0f);
        gemm_hs<<<grid, blk, SMEM_G>>>(xh, xl, kwh, kwl, tk, D_, D_, kb, 1.0f);
        gemm_hs<<<grid, blk, SMEM_G>>>(xh, xl, vwh, vwl, tv, D_, D_, vb, 1.0f);
    }

    // 4: RoPE (q,k) + permute, split; V transpose to [B,H,Dh,S], split
    {
        const long total = (long)B_ * H_ * S_ * (DH / 2);
        rope_permute_kernel<<<(unsigned)((total + 255) / 256), blk>>>();
        dim3 gv(S_ / 32, DH / 32, B_ * H_);
        vtrans_kernel<<<gv, dim3(32, 8)>>>();
    }

    // 5: fused flash attention -> ctx split fp16 [B,S,D]
    {
        dim3 grid(S_ / 128, B_ * H_);
        flash_kernel<<<grid, blk, SMEM_F>>>(qh, ql, kh, kl, vth, vtl, ctxh, ctxl);
    }

    // 6: out = ctx @ out_w^T + out_b (fp32 out)
    {
        dim3 grid(D_ / 128, MROWS / 128, 1);
        gemm_hs<<<grid, blk, SMEM_G>>>(ctxh, ctxl, owh, owl, out, D_, D_, ob, 1.0f);
    }
}